// round 5
// baseline (speedup 1.0000x reference)
#include <cuda_runtime.h>

#define T_LEN 256
#define HID   20
#define FFD   64

// ---------- packed fp32x2 FMA (sm_103a; PTX-only path) ----------
union F2U { float2 f; unsigned long long u; };

__device__ __forceinline__ float2 ffma2(float2 a, float2 b, float2 c) {
    F2U A, B, C, D;
    A.f = a; B.f = b; C.f = c;
    asm("fma.rn.f32x2 %0, %1, %2, %3;" : "=l"(D.u) : "l"(A.u), "l"(B.u), "l"(C.u));
    return D.f;
}

__device__ __forceinline__ float tanhap(float x) {
    float r; asm("tanh.approx.f32 %0, %1;" : "=f"(r) : "f"(x)); return r;
}
// sigmoid(x) = 0.5 * tanh(x/2) + 0.5
__device__ __forceinline__ float sigm(float x) {
    return fmaf(0.5f, tanhap(0.5f * x), 0.5f);
}

// cell state in shared: pair p in {0:c1r0, 1:c1r1, 2:c2r0, 3:c2r1}
#define SC(p, j) s_c[((((p) * HID) + (j)) << 7) | tid]

__global__ void __launch_bounds__(128, 3) lstm2_head_kernel(
    const float* __restrict__ diag,
    const float* __restrict__ W_ih1, const float* __restrict__ W_hh1,
    const float* __restrict__ b_ih1, const float* __restrict__ b_hh1,
    const float* __restrict__ W_ih2, const float* __restrict__ W_hh2,
    const float* __restrict__ b_ih2, const float* __restrict__ b_hh2,
    const float* __restrict__ W1,   const float* __restrict__ b1,
    const float* __restrict__ W2,   const float* __restrict__ b2,
    float* __restrict__ out, int rows)
{
    // Gate-quad weight layout: s_w[j][k] = (Wi[j][k], Wf[j][k], Wg[j][k], Wo[j][k])
    __shared__ float4 s_w1[HID][HID];       // layer1 recurrent  (6.4 KB)
    __shared__ float4 s_w2[HID][2 * HID];   // layer2 [h1new | h2old] (12.8 KB)
    __shared__ float4 s_wx1[HID];           // layer1 input weights (in_dim=1)
    __shared__ float4 s_bq1[HID];           // summed biases, quad layout
    __shared__ float4 s_bq2[HID];
    __shared__ float  s_W1f[FFD * HID];
    __shared__ float  s_b1f[FFD];
    __shared__ float  s_W2f[FFD];
    __shared__ float  s_b2f;
    extern __shared__ float s_c[];          // 4*HID*128 floats = 40 KB

    const int tid = threadIdx.x;
    const int bd  = blockDim.x;

    for (int idx = tid; idx < HID * HID; idx += bd) {
        int j = idx / HID, k = idx % HID;
        s_w1[j][k] = make_float4(W_hh1[(j      ) * HID + k],
                                 W_hh1[(HID + j) * HID + k],
                                 W_hh1[(2*HID+j) * HID + k],
                                 W_hh1[(3*HID+j) * HID + k]);
    }
    for (int idx = tid; idx < HID * 2 * HID; idx += bd) {
        int j = idx / (2 * HID), k = idx % (2 * HID);
        const float* Wm = (k < HID) ? W_ih2 : W_hh2;
        int kk = (k < HID) ? k : (k - HID);
        s_w2[j][k] = make_float4(Wm[(j      ) * HID + kk],
                                 Wm[(HID + j) * HID + kk],
                                 Wm[(2*HID+j) * HID + kk],
                                 Wm[(3*HID+j) * HID + kk]);
    }
    for (int j = tid; j < HID; j += bd) {
        s_wx1[j] = make_float4(W_ih1[j], W_ih1[HID + j], W_ih1[2*HID + j], W_ih1[3*HID + j]);
        s_bq1[j] = make_float4(b_ih1[j]       + b_hh1[j],
                               b_ih1[HID+j]   + b_hh1[HID+j],
                               b_ih1[2*HID+j] + b_hh1[2*HID+j],
                               b_ih1[3*HID+j] + b_hh1[3*HID+j]);
        s_bq2[j] = make_float4(b_ih2[j]       + b_hh2[j],
                               b_ih2[HID+j]   + b_hh2[HID+j],
                               b_ih2[2*HID+j] + b_hh2[2*HID+j],
                               b_ih2[3*HID+j] + b_hh2[3*HID+j]);
    }
    for (int i = tid; i < FFD * HID; i += bd) s_W1f[i] = W1[i];
    for (int i = tid; i < FFD; i += bd) { s_b1f[i] = b1[i]; s_W2f[i] = W2[i]; }
    if (tid == 0) s_b2f = b2[0];

    // zero own cell-state slots
#pragma unroll
    for (int p = 0; p < 4; p++)
#pragma unroll
        for (int j = 0; j < HID; j++) SC(p, j) = 0.0f;
    __syncthreads();

    // Two batch rows per thread.
    const int tix = blockIdx.x * bd + tid;
    const int r0 = 2 * tix, r1 = 2 * tix + 1;
    if (r0 >= rows) return;

    float h1[2][HID], h2[2][HID];
#pragma unroll
    for (int j = 0; j < HID; j++) {
        h1[0][j] = 0.f; h2[0][j] = 0.f;
        h1[1][j] = 0.f; h2[1][j] = 0.f;
    }

    const float* __restrict__ x0p = diag + (size_t)r0 * T_LEN;
    const float* __restrict__ x1p = diag + (size_t)r1 * T_LEN;

#pragma unroll 1
    for (int t = 0; t < T_LEN; t++) {
        const float x0 = __ldg(x0p + t);
        const float x1 = __ldg(x1p + t);
        float h1n[2][HID], h2n[2][HID];

        // ---- layer 1: per-j gate-quad accumulation, both rows share weights ----
#pragma unroll
        for (int j = 0; j < HID; j++) {
            float4 wx = s_wx1[j];
            float4 bq = s_bq1[j];
            float2 wif = make_float2(wx.x, wx.y), wgo = make_float2(wx.z, wx.w);
            float2 bif = make_float2(bq.x, bq.y), bgo = make_float2(bq.z, bq.w);
            float2 zif0 = ffma2(wif, make_float2(x0, x0), bif);
            float2 zgo0 = ffma2(wgo, make_float2(x0, x0), bgo);
            float2 zif1 = ffma2(wif, make_float2(x1, x1), bif);
            float2 zgo1 = ffma2(wgo, make_float2(x1, x1), bgo);
#pragma unroll
            for (int k = 0; k < HID; k++) {
                float4 w = s_w1[j][k];
                float2 a = make_float2(w.x, w.y), bb = make_float2(w.z, w.w);
                float2 h0 = make_float2(h1[0][k], h1[0][k]);
                float2 hh = make_float2(h1[1][k], h1[1][k]);
                zif0 = ffma2(a, h0, zif0);  zgo0 = ffma2(bb, h0, zgo0);
                zif1 = ffma2(a, hh, zif1);  zgo1 = ffma2(bb, hh, zgo1);
            }
            {
                float ii = sigm(zif0.x), ff = sigm(zif0.y);
                float gg = tanhap(zgo0.x), oo = sigm(zgo0.y);
                float cc = fmaf(ff, SC(0, j), ii * gg);
                SC(0, j) = cc; h1n[0][j] = oo * tanhap(cc);
            }
            {
                float ii = sigm(zif1.x), ff = sigm(zif1.y);
                float gg = tanhap(zgo1.x), oo = sigm(zgo1.y);
                float cc = fmaf(ff, SC(1, j), ii * gg);
                SC(1, j) = cc; h1n[1][j] = oo * tanhap(cc);
            }
        }
#pragma unroll
        for (int j = 0; j < HID; j++) { h1[0][j] = h1n[0][j]; h1[1][j] = h1n[1][j]; }

        // ---- layer 2 ----
#pragma unroll
        for (int j = 0; j < HID; j++) {
            float4 bq = s_bq2[j];
            float2 zif0 = make_float2(bq.x, bq.y), zgo0 = make_float2(bq.z, bq.w);
            float2 zif1 = zif0, zgo1 = zgo0;
#pragma unroll
            for (int k = 0; k < HID; k++) {
                float4 w = s_w2[j][k];
                float2 a = make_float2(w.x, w.y), bb = make_float2(w.z, w.w);
                float2 h0 = make_float2(h1[0][k], h1[0][k]);
                float2 hh = make_float2(h1[1][k], h1[1][k]);
                zif0 = ffma2(a, h0, zif0);  zgo0 = ffma2(bb, h0, zgo0);
                zif1 = ffma2(a, hh, zif1);  zgo1 = ffma2(bb, hh, zgo1);
            }
#pragma unroll
            for (int k = 0; k < HID; k++) {
                float4 w = s_w2[j][HID + k];
                float2 a = make_float2(w.x, w.y), bb = make_float2(w.z, w.w);
                float2 h0 = make_float2(h2[0][k], h2[0][k]);
                float2 hh = make_float2(h2[1][k], h2[1][k]);
                zif0 = ffma2(a, h0, zif0);  zgo0 = ffma2(bb, h0, zgo0);
                zif1 = ffma2(a, hh, zif1);  zgo1 = ffma2(bb, hh, zgo1);
            }
            {
                float ii = sigm(zif0.x), ff = sigm(zif0.y);
                float gg = tanhap(zgo0.x), oo = sigm(zgo0.y);
                float cc = fmaf(ff, SC(2, j), ii * gg);
                SC(2, j) = cc; h2n[0][j] = oo * tanhap(cc);
            }
            {
                float ii = sigm(zif1.x), ff = sigm(zif1.y);
                float gg = tanhap(zgo1.x), oo = sigm(zgo1.y);
                float cc = fmaf(ff, SC(3, j), ii * gg);
                SC(3, j) = cc; h2n[1][j] = oo * tanhap(cc);
            }
        }
#pragma unroll
        for (int j = 0; j < HID; j++) { h2[0][j] = h2n[0][j]; h2[1][j] = h2n[1][j]; }
    }

    // ---- head: relu(relu(h2 @ W1^T + b1) @ W2^T + b2), both rows ----
    float acc0 = s_b2f, acc1 = s_b2f;
#pragma unroll 1
    for (int n = 0; n < FFD; n++) {
        float a0 = s_b1f[n], a1 = s_b1f[n];
#pragma unroll
        for (int k = 0; k < HID; k++) {
            float w = s_W1f[n * HID + k];
            a0 = fmaf(w, h2[0][k], a0);
            a1 = fmaf(w, h2[1][k], a1);
        }
        float w2v = s_W2f[n];
        acc0 = fmaf(w2v, fmaxf(a0, 0.0f), acc0);
        acc1 = fmaf(w2v, fmaxf(a1, 0.0f), acc1);
    }
    out[r0] = fmaxf(acc0, 0.0f);
    if (r1 < rows) out[r1] = fmaxf(acc1, 0.0f);
}

extern "C" void kernel_launch(void* const* d_in, const int* in_sizes, int n_in,
                              void* d_out, int out_size) {
    const float* diag  = (const float*)d_in[0];
    const float* W_ih1 = (const float*)d_in[1];
    const float* W_hh1 = (const float*)d_in[2];
    const float* b_ih1 = (const float*)d_in[3];
    const float* b_hh1 = (const float*)d_in[4];
    const float* W_ih2 = (const float*)d_in[5];
    const float* W_hh2 = (const float*)d_in[6];
    const float* b_ih2 = (const float*)d_in[7];
    const float* b_hh2 = (const float*)d_in[8];
    const float* W1    = (const float*)d_in[9];
    const float* b1    = (const float*)d_in[10];
    const float* W2    = (const float*)d_in[11];
    const float* b2    = (const float*)d_in[12];

    int rows = out_size;              // B = 131072
    int threads = 128;
    int rows_per_block = threads * 2; // 2 rows per thread
    int blocks = (rows + rows_per_block - 1) / rows_per_block;
    size_t dyn_smem = 4 * HID * 128 * sizeof(float);  // 40 KB cell-state

    // Opt in to static+dynamic > 48 KB. Host-side attribute set: not a stream
    // op, not an allocation — legal during graph capture, idempotent.
    cudaFuncSetAttribute(lstm2_head_kernel,
                         cudaFuncAttributeMaxDynamicSharedMemorySize,
                         (int)dyn_smem);

    lstm2_head_kernel<<<blocks, threads, dyn_smem>>>(
        diag, W_ih1, W_hh1, b_ih1, b_hh1,
        W_ih2, W_hh2, b_ih2, b_hh2,
        W1, b1, W2, b2, (float*)d_out, rows);
}

// round 7
// speedup vs baseline: 1.5628x; 1.5628x over previous
#include <cuda_runtime.h>
#include <cuda_bf16.h>
#include <cstdint>

#define T_LEN 256
#define HID   20
#define FFD   64
#define ZSTRIDE 336    // 84 floats, 16B-multiple, conflict-free row shift

// dynamic smem offsets (from 128-aligned base)
#define A1_OFF   0        // [128][64 bf16] rows=batch, cols=[h1_hi(20)|h1_lo(20)|h1_hi(20)|xh,xl,xh,pad]
#define A2_OFF   16384    // [128][64 bf16] [h2_hi|h2_lo|h2_hi|pad4]
#define B1_OFF   32768    // [80][64 bf16]  rows=gates: [Whh1_hi|Whh1_hi|Whh1_lo|Wx_hi,Wx_hi,Wx_lo,0]
#define B2A_OFF  43008    // [80][64]       [Wih2_hi|Wih2_hi|Wih2_lo|0]
#define B2B_OFF  53248    // [80][64]       [Whh2_hi|Whh2_hi|Whh2_lo|0]
#define Z_OFF    63488    // [128][ZSTRIDE bytes] fp32 z buffer
#define BQ1_OFF  106496   // 20 x float4 gate-quad biases
#define BQ2_OFF  106816
#define W1F_OFF  107136   // head W1 [64][20] f32
#define B1F_OFF  112256
#define W2F_OFF  112512
#define B2F_OFF  112768
#define DYN_BYTES 113664

#define SWZ(row, b) ((b) ^ (((row) & 7) << 4))

__device__ __forceinline__ float tanhap(float x) {
    float r; asm("tanh.approx.f32 %0, %1;" : "=f"(r) : "f"(x)); return r;
}
__device__ __forceinline__ float sigm(float x) {
    return fmaf(0.5f, tanhap(0.5f * x), 0.5f);
}
// pack two f32 -> bf16x2; upper half = hi_val, lower half = lo_val
__device__ __forceinline__ uint32_t pack2(float hi_val, float lo_val) {
    uint32_t r;
    asm("cvt.rn.bf16x2.f32 %0, %1, %2;" : "=r"(r) : "f"(hi_val), "f"(lo_val));
    return r;
}
__device__ __forceinline__ void ldsm4(uint32_t* r, uint32_t a) {
    asm volatile("ldmatrix.sync.aligned.m8n8.x4.shared.b16 {%0,%1,%2,%3}, [%4];"
                 : "=r"(r[0]), "=r"(r[1]), "=r"(r[2]), "=r"(r[3]) : "r"(a));
}
__device__ __forceinline__ void mma16816(float* c, const uint32_t* a, const uint32_t* b) {
    asm volatile(
        "mma.sync.aligned.m16n8k16.row.col.f32.bf16.bf16.f32 "
        "{%0,%1,%2,%3}, {%4,%5,%6,%7}, {%8,%9}, {%0,%1,%2,%3};"
        : "+f"(c[0]), "+f"(c[1]), "+f"(c[2]), "+f"(c[3])
        : "r"(a[0]), "r"(a[1]), "r"(a[2]), "r"(a[3]), "r"(b[0]), "r"(b[1]));
}

// A fragment address (row-major [row][64 bf16], 128B rows, SW128):
// lanes 0-7: (m0+lr, k0) | 8-15: (m8+lr, k0) | 16-23: (m0+lr, k8) | 24-31: (m8+lr, k8)
__device__ __forceinline__ uint32_t a_addr(uint32_t base, int mt, int ks, int lane) {
    int sub = lane >> 3, lr = lane & 7;
    int row = mt * 16 + ((sub & 1) << 3) + lr;
    int cb  = ks * 32 + ((sub >> 1) << 4);
    return base + row * 128 + SWZ(row, cb);
}
// B fragment address (W stored [n][k] row-major -> non-trans ldmatrix gives b-frag):
// lanes 0-7: (n0+lr, k0) | 8-15: (n0+lr, k8) | 16-23: (n8+lr, k0) | 24-31: (n8+lr, k8)
// regs {0,1} = b-frag n-tile 2np, regs {2,3} = n-tile 2np+1 (both k-step ks)
__device__ __forceinline__ uint32_t b_addr(uint32_t base, int np, int ks, int lane) {
    int sub = lane >> 3, lr = lane & 7;
    int row = np * 16 + ((sub >> 1) << 3) + lr;
    int cb  = ks * 32 + ((sub & 1) << 4);
    return base + row * 128 + SWZ(row, cb);
}

// one K=64 GEMM pass: accumulate into cacc[2 m-tiles][10 n-tiles][4]
__device__ __forceinline__ void gemm_k64(float cacc[2][10][4], uint32_t aB, uint32_t bB, int lane) {
#pragma unroll
    for (int ks = 0; ks < 4; ks++) {
        uint32_t a0[4], a1[4];
        ldsm4(a0, a_addr(aB, 0, ks, lane));
        ldsm4(a1, a_addr(aB, 1, ks, lane));
#pragma unroll
        for (int np = 0; np < 5; np++) {
            uint32_t b[4];
            ldsm4(b, b_addr(bB, np, ks, lane));
            mma16816(cacc[0][2*np],     a0, b);
            mma16816(cacc[0][2*np + 1], a0, b + 2);
            mma16816(cacc[1][2*np],     a1, b);
            mma16816(cacc[1][2*np + 1], a1, b + 2);
        }
    }
}

__device__ __forceinline__ void store_z(float cacc[2][10][4], char* sm, int Rw, int lane) {
#pragma unroll
    for (int mt = 0; mt < 2; mt++)
#pragma unroll
        for (int nt = 0; nt < 10; nt++) {
            int r0 = Rw + mt * 16 + (lane >> 2);
            int cb = (nt * 8 + 2 * (lane & 3)) * 4;
            *(float2*)(sm + Z_OFF + r0 * ZSTRIDE + cb) =
                make_float2(cacc[mt][nt][0], cacc[mt][nt][1]);
            *(float2*)(sm + Z_OFF + (r0 + 8) * ZSTRIDE + cb) =
                make_float2(cacc[mt][nt][2], cacc[mt][nt][3]);
        }
}

// epilogue for one layer: z -> activations -> c update -> h written as bf16 hi/lo to A tile row
__device__ __forceinline__ void epilogue(const char* zrow, const float4* bq, float* cs,
                                         char* arow, int lane) {
#pragma unroll
    for (int q = 0; q < 10; q++) {
        float2 zi = *(const float2*)(zrow + 8 * q);
        float2 zf = *(const float2*)(zrow + 80 + 8 * q);
        float2 zg = *(const float2*)(zrow + 160 + 8 * q);
        float2 zo = *(const float2*)(zrow + 240 + 8 * q);
        float4 ba = bq[2 * q], bb = bq[2 * q + 1];
        float i0 = sigm(zi.x + ba.x),   i1 = sigm(zi.y + bb.x);
        float f0 = sigm(zf.x + ba.y),   f1 = sigm(zf.y + bb.y);
        float g0 = tanhap(zg.x + ba.z), g1 = tanhap(zg.y + bb.z);
        float o0 = sigm(zo.x + ba.w),   o1 = sigm(zo.y + bb.w);
        float cc0 = fmaf(f0, cs[2*q],     i0 * g0); cs[2*q]     = cc0;
        float cc1 = fmaf(f1, cs[2*q + 1], i1 * g1); cs[2*q + 1] = cc1;
        float h0 = o0 * tanhap(cc0);
        float h1 = o1 * tanhap(cc1);
        uint32_t hi = pack2(h1, h0);
        float r0f = __uint_as_float(hi << 16);
        float r1f = __uint_as_float(hi & 0xFFFF0000u);
        uint32_t lo = pack2(h1 - r1f, h0 - r0f);
        *(uint32_t*)(arow + SWZ(lane, 4 * q))      = hi;   // hi block (cols 0-19)
        *(uint32_t*)(arow + SWZ(lane, 40 + 4 * q)) = lo;   // lo block (cols 20-39)
        *(uint32_t*)(arow + SWZ(lane, 80 + 4 * q)) = hi;   // hi dup  (cols 40-59)
    }
}

__global__ void __launch_bounds__(128, 2) lstm2_mma_kernel(
    const float* __restrict__ diag,
    const float* __restrict__ W_ih1, const float* __restrict__ W_hh1,
    const float* __restrict__ b_ih1, const float* __restrict__ b_hh1,
    const float* __restrict__ W_ih2, const float* __restrict__ W_hh2,
    const float* __restrict__ b_ih2, const float* __restrict__ b_hh2,
    const float* __restrict__ W1,   const float* __restrict__ b1,
    const float* __restrict__ W2,   const float* __restrict__ b2,
    float* __restrict__ out, int rows)
{
    extern __shared__ char rawsm[];
    char* sm = (char*)(((uintptr_t)rawsm + 127) & ~(uintptr_t)127);
    const uint32_t smb = (uint32_t)__cvta_generic_to_shared(sm);

    const int tid = threadIdx.x;
    const int lane = tid & 31;
    const int wid = tid >> 5;
    const int Rw = wid * 32;

    // ---- zero A1+A2 ----
    for (int i = tid; i < 32768 / 4; i += 128) *(uint32_t*)(sm + A1_OFF + 4 * i) = 0;

    // ---- stage B1/B2a/B2b (hi/lo split + swizzle) ----
    for (int idx = tid; idx < 80 * 64; idx += 128) {
        int n = idx >> 6, k = idx & 63;
        int off = n * 128 + SWZ(n, 2 * k);
        // layer 1
        float v; bool lo;
        if (k < 20)      { v = W_hh1[n * HID + k];      lo = false; }
        else if (k < 40) { v = W_hh1[n * HID + k - 20]; lo = false; }
        else if (k < 60) { v = W_hh1[n * HID + k - 40]; lo = true;  }
        else if (k < 62) { v = W_ih1[n];                lo = false; }
        else if (k == 62){ v = W_ih1[n];                lo = true;  }
        else             { v = 0.f;                     lo = false; }
        __nv_bfloat16 vh = __float2bfloat16(v);
        *(__nv_bfloat16*)(sm + B1_OFF + off) =
            lo ? __float2bfloat16(v - __bfloat162float(vh)) : vh;
        // layer 2 (B2a = W_ih2 applied to A1's h1 columns; B2b = W_hh2 on A2's h2)
        float va = (k < 20) ? W_ih2[n * HID + k] : (k < 40) ? W_ih2[n * HID + k - 20]
                 : (k < 60) ? W_ih2[n * HID + k - 40] : 0.f;
        float vb = (k < 20) ? W_hh2[n * HID + k] : (k < 40) ? W_hh2[n * HID + k - 20]
                 : (k < 60) ? W_hh2[n * HID + k - 40] : 0.f;
        bool lo2 = (k >= 40 && k < 60);
        __nv_bfloat16 vah = __float2bfloat16(va), vbh = __float2bfloat16(vb);
        *(__nv_bfloat16*)(sm + B2A_OFF + off) =
            lo2 ? __float2bfloat16(va - __bfloat162float(vah)) : vah;
        *(__nv_bfloat16*)(sm + B2B_OFF + off) =
            lo2 ? __float2bfloat16(vb - __bfloat162float(vbh)) : vbh;
    }
    // biases + head weights
    for (int j = tid; j < HID; j += 128) {
        ((float4*)(sm + BQ1_OFF))[j] = make_float4(
            b_ih1[j] + b_hh1[j], b_ih1[HID + j] + b_hh1[HID + j],
            b_ih1[2*HID + j] + b_hh1[2*HID + j], b_ih1[3*HID + j] + b_hh1[3*HID + j]);
        ((float4*)(sm + BQ2_OFF))[j] = make_float4(
            b_ih2[j] + b_hh2[j], b_ih2[HID + j] + b_hh2[HID + j],
            b_ih2[2*HID + j] + b_hh2[2*HID + j], b_ih2[3*HID + j] + b_hh2[3*HID + j]);
    }
    for (int i = tid; i < FFD * HID; i += 128) ((float*)(sm + W1F_OFF))[i] = W1[i];
    for (int i = tid; i < FFD; i += 128) {
        ((float*)(sm + B1F_OFF))[i] = b1[i];
        ((float*)(sm + W2F_OFF))[i] = W2[i];
    }
    if (tid == 0) *((float*)(sm + B2F_OFF)) = b2[0];
    __syncthreads();   // zero-fill complete before x0 staging (avoids write race)

    const int row_g = blockIdx.x * 128 + tid;
    const float* __restrict__ xrow = diag + (size_t)min(row_g, rows - 1) * T_LEN;
    char* A1row = sm + A1_OFF + tid * 128;
    char* A2row = sm + A2_OFF + tid * 128;
    const char* zrow = sm + Z_OFF + tid * ZSTRIDE;

    {   // stage x_0: cols 60=x_hi, 61=x_lo, 62=x_hi, 63=0
        float xv = __ldg(xrow);
        __nv_bfloat16 xh = __float2bfloat16(xv);
        float xhf = __bfloat162float(xh);
        *(uint32_t*)(A1row + SWZ(lane, 120)) = pack2(xv - xhf, xhf);
        *(uint32_t*)(A1row + SWZ(lane, 124)) = (uint32_t)__bfloat16_as_ushort(xh);
    }
    __syncthreads();

    const uint32_t A1w = smb + A1_OFF + Rw * 128;
    const uint32_t A2w = smb + A2_OFF + Rw * 128;
    const float4* bq1 = (const float4*)(sm + BQ1_OFF);
    const float4* bq2 = (const float4*)(sm + BQ2_OFF);

    float c1s[HID], c2s[HID];
#pragma unroll
    for (int j = 0; j < HID; j++) { c1s[j] = 0.f; c2s[j] = 0.f; }

#pragma unroll 1
    for (int t = 0; t < T_LEN; t++) {
        float cacc[2][10][4];

        // ---- layer 1: z1 = A1 x B1^T ----
#pragma unroll
        for (int mt = 0; mt < 2; mt++)
#pragma unroll
            for (int nt = 0; nt < 10; nt++)
#pragma unroll
                for (int e = 0; e < 4; e++) cacc[mt][nt][e] = 0.f;
        gemm_k64(cacc, A1w, smb + B1_OFF, lane);
        store_z(cacc, sm, Rw, lane);
        __syncwarp();
        epilogue(zrow, bq1, c1s, A1row, lane);   // h1(t) -> A1
        __syncwarp();

        // ---- layer 2: z2 = A1 x B2a^T + A2 x B2b^T ----
#pragma unroll
        for (int mt = 0; mt < 2; mt++)
#pragma unroll
            for (int nt = 0; nt < 10; nt++)
#pragma unroll
                for (int e = 0; e < 4; e++) cacc[mt][nt][e] = 0.f;
        gemm_k64(cacc, A1w, smb + B2A_OFF, lane);
        gemm_k64(cacc, A2w, smb + B2B_OFF, lane);
        store_z(cacc, sm, Rw, lane);
        __syncwarp();
        epilogue(zrow, bq2, c2s, A2row, lane);   // h2(t) -> A2
        if (t + 1 < T_LEN) {                      // stage x_{t+1}
            float xv = __ldg(xrow + t + 1);
            __nv_bfloat16 xh = __float2bfloat16(xv);
            float xhf = __bfloat162float(xh);
            *(uint32_t*)(A1row + SWZ(lane, 120)) = pack2(xv - xhf, xhf);
            *(uint32_t*)(A1row + SWZ(lane, 124)) = (uint32_t)__bfloat16_as_ushort(xh);
        }
        __syncwarp();
    }

    // ---- head: reconstruct h2 = hi + lo from A2, then 20->64->1 ReLU MLP ----
    float h2f[HID];
#pragma unroll
    for (int q = 0; q < 10; q++) {
        uint32_t hi = *(uint32_t*)(A2row + SWZ(lane, 4 * q));
        uint32_t lo = *(uint32_t*)(A2row + SWZ(lane, 40 + 4 * q));
        h2f[2*q]     = __uint_as_float(hi << 16) + __uint_as_float(lo << 16);
        h2f[2*q + 1] = __uint_as_float(hi & 0xFFFF0000u) + __uint_as_float(lo & 0xFFFF0000u);
    }
    const float* W1f = (const float*)(sm + W1F_OFF);
    const float* b1f = (const float*)(sm + B1F_OFF);
    const float* W2f = (const float*)(sm + W2F_OFF);
    float acc2 = *((const float*)(sm + B2F_OFF));
#pragma unroll 1
    for (int n = 0; n < FFD; n++) {
        float a = b1f[n];
#pragma unroll
        for (int k = 0; k < HID; k++) a = fmaf(W1f[n * HID + k], h2f[k], a);
        acc2 = fmaf(W2f[n], fmaxf(a, 0.0f), acc2);
    }
    if (row_g < rows) out[row_g] = fmaxf(acc2, 0.0f);
}

extern "C" void kernel_launch(void* const* d_in, const int* in_sizes, int n_in,
                              void* d_out, int out_size) {
    const float* diag  = (const float*)d_in[0];
    const float* W_ih1 = (const float*)d_in[1];
    const float* W_hh1 = (const float*)d_in[2];
    const float* b_ih1 = (const float*)d_in[3];
    const float* b_hh1 = (const float*)d_in[4];
    const float* W_ih2 = (const float*)d_in[5];
    const float* W_hh2 = (const float*)d_in[6];
    const float* b_ih2 = (const float*)d_in[7];
    const float* b_hh2 = (const float*)d_in[8];
    const float* W1    = (const float*)d_in[9];
    const float* b1    = (const float*)d_in[10];
    const float* W2    = (const float*)d_in[11];
    const float* b2    = (const float*)d_in[12];

    int rows = out_size;   // 131072
    int blocks = (rows + 127) / 128;

    cudaFuncSetAttribute(lstm2_mma_kernel,
                         cudaFuncAttributeMaxDynamicSharedMemorySize, DYN_BYTES);

    lstm2_mma_kernel<<<blocks, 128, DYN_BYTES>>>(
        diag, W_ih1, W_hh1, b_ih1, b_hh1,
        W_ih2, W_hh2, b_ih2, b_hh2,
        W1, b1, W2, b2, (float*)d_out, rows);
}

// round 8
// speedup vs baseline: 2.1203x; 1.3567x over previous
#include <cuda_runtime.h>
#include <cuda_bf16.h>
#include <cstdint>

#define T_LEN 256
#define HID   20
#define FFD   64
#define ZSTRIDE 336    // 84 floats, 16B-multiple

// dynamic smem offsets (from 128-aligned base)
#define A1_OFF   0        // [128][64 bf16] rows=batch: [h1_hi(20)|h1_lo(20)|h1_hi(20)|xh,xl,xh,pad]
#define A2_OFF   16384    // [128][64 bf16] [h2_hi|h2_lo|h2_hi|pad4]
#define B1_OFF   32768    // [80][64 bf16]  [Whh1_hi|Whh1_hi|Whh1_lo|Wx_hi,Wx_hi,Wx_lo,0]
#define B2A_OFF  43008    // [80][64]       [Wih2_hi|Wih2_hi|Wih2_lo|0]
#define B2B_OFF  53248    // [80][64]       [Whh2_hi|Whh2_hi|Whh2_lo|0]
#define Z_OFF    63488    // [128][ZSTRIDE bytes] fp32 z
#define BQ1_OFF  106496   // 20 x float4 gate-quad biases
#define BQ2_OFF  106816
#define W1F_OFF  107136   // head W1 [64][20] f32
#define B1F_OFF  112256
#define W2F_OFF  112512
#define B2F_OFF  112768
#define DYN_BYTES 113664

#define SWZ(row, b) ((b) ^ (((row) & 7) << 4))

__device__ __forceinline__ float tanhap(float x) {
    float r; asm("tanh.approx.f32 %0, %1;" : "=f"(r) : "f"(x)); return r;
}
__device__ __forceinline__ float sigm(float x) {
    return fmaf(0.5f, tanhap(0.5f * x), 0.5f);
}
__device__ __forceinline__ uint32_t pack2(float hi_val, float lo_val) {
    uint32_t r;
    asm("cvt.rn.bf16x2.f32 %0, %1, %2;" : "=r"(r) : "f"(hi_val), "f"(lo_val));
    return r;
}
__device__ __forceinline__ void ldsm4(uint32_t* r, uint32_t a) {
    asm volatile("ldmatrix.sync.aligned.m8n8.x4.shared.b16 {%0,%1,%2,%3}, [%4];"
                 : "=r"(r[0]), "=r"(r[1]), "=r"(r[2]), "=r"(r[3]) : "r"(a));
}
__device__ __forceinline__ void mma16816(float* c, const uint32_t* a, const uint32_t* b) {
    asm volatile(
        "mma.sync.aligned.m16n8k16.row.col.f32.bf16.bf16.f32 "
        "{%0,%1,%2,%3}, {%4,%5,%6,%7}, {%8,%9}, {%0,%1,%2,%3};"
        : "+f"(c[0]), "+f"(c[1]), "+f"(c[2]), "+f"(c[3])
        : "r"(a[0]), "r"(a[1]), "r"(a[2]), "r"(a[3]), "r"(b[0]), "r"(b[1]));
}

// A fragment address for a 16-row tile at 'base' (row-major 128B rows, SW128)
__device__ __forceinline__ uint32_t a_addr(uint32_t base, int ks, int lane) {
    int sub = lane >> 3, lr = lane & 7;
    int row = ((sub & 1) << 3) + lr;
    int cb  = ks * 32 + ((sub >> 1) << 4);
    return base + row * 128 + SWZ(row, cb);
}
// B fragment address (W stored [n][k] row-major): regs {0,1}=n-tile 2np, {2,3}=2np+1
__device__ __forceinline__ uint32_t b_addr(uint32_t base, int np, int ks, int lane) {
    int sub = lane >> 3, lr = lane & 7;
    int row = np * 16 + ((sub >> 1) << 3) + lr;
    int cb  = ks * 32 + ((sub & 1) << 4);
    return base + row * 128 + SWZ(row, cb);
}

// one K=64 pass for M=16: accumulate into cacc[10][4]
__device__ __forceinline__ void gemm_k64(float cacc[10][4], uint32_t aB, uint32_t bB, int lane) {
#pragma unroll
    for (int ks = 0; ks < 4; ks++) {
        uint32_t a0[4];
        ldsm4(a0, a_addr(aB, ks, lane));
#pragma unroll
        for (int np = 0; np < 5; np++) {
            uint32_t b[4];
            ldsm4(b, b_addr(bB, np, ks, lane));
            mma16816(cacc[2*np],     a0, b);
            mma16816(cacc[2*np + 1], a0, b + 2);
        }
    }
}

__device__ __forceinline__ void store_z(float cacc[10][4], char* sm, int Rw, int lane) {
    int r0 = Rw + (lane >> 2);
    int cb = 2 * (lane & 3) * 4;
#pragma unroll
    for (int nt = 0; nt < 10; nt++) {
        *(float2*)(sm + Z_OFF + r0 * ZSTRIDE + nt * 32 + cb) =
            make_float2(cacc[nt][0], cacc[nt][1]);
        *(float2*)(sm + Z_OFF + (r0 + 8) * ZSTRIDE + nt * 32 + cb) =
            make_float2(cacc[nt][2], cacc[nt][3]);
    }
}

// epilogue: this thread handles 5 gate-quads [qs, qs+5) of row 'rE' (10 hidden units)
__device__ __forceinline__ void epilogue(const char* zrow, const float4* bq, float* cs,
                                         char* arow, int rE, int qs) {
#pragma unroll
    for (int qi = 0; qi < 5; qi++) {
        int q = qs + qi;
        float2 zi = *(const float2*)(zrow + 8 * q);
        float2 zf = *(const float2*)(zrow + 80 + 8 * q);
        float2 zg = *(const float2*)(zrow + 160 + 8 * q);
        float2 zo = *(const float2*)(zrow + 240 + 8 * q);
        float4 ba = bq[2 * q], bb = bq[2 * q + 1];
        float i0 = sigm(zi.x + ba.x),   i1 = sigm(zi.y + bb.x);
        float f0 = sigm(zf.x + ba.y),   f1 = sigm(zf.y + bb.y);
        float g0 = tanhap(zg.x + ba.z), g1 = tanhap(zg.y + bb.z);
        float o0 = sigm(zo.x + ba.w),   o1 = sigm(zo.y + bb.w);
        float cc0 = fmaf(f0, cs[2*qi],     i0 * g0); cs[2*qi]     = cc0;
        float cc1 = fmaf(f1, cs[2*qi + 1], i1 * g1); cs[2*qi + 1] = cc1;
        float h0 = o0 * tanhap(cc0);
        float h1 = o1 * tanhap(cc1);
        uint32_t hi = pack2(h1, h0);
        float r0f = __uint_as_float(hi << 16);
        float r1f = __uint_as_float(hi & 0xFFFF0000u);
        uint32_t lo = pack2(h1 - r1f, h0 - r0f);
        *(uint32_t*)(arow + SWZ(rE, 4 * q))      = hi;   // hi (cols 0-19)
        *(uint32_t*)(arow + SWZ(rE, 40 + 4 * q)) = lo;   // lo (cols 20-39)
        *(uint32_t*)(arow + SWZ(rE, 80 + 4 * q)) = hi;   // hi dup (cols 40-59)
    }
}

__global__ void __launch_bounds__(256, 2) lstm2_mma_kernel(
    const float* __restrict__ diag,
    const float* __restrict__ W_ih1, const float* __restrict__ W_hh1,
    const float* __restrict__ b_ih1, const float* __restrict__ b_hh1,
    const float* __restrict__ W_ih2, const float* __restrict__ W_hh2,
    const float* __restrict__ b_ih2, const float* __restrict__ b_hh2,
    const float* __restrict__ W1,   const float* __restrict__ b1,
    const float* __restrict__ W2,   const float* __restrict__ b2,
    float* __restrict__ out, int rows)
{
    extern __shared__ char rawsm[];
    char* sm = (char*)(((uintptr_t)rawsm + 127) & ~(uintptr_t)127);
    const uint32_t smb = (uint32_t)__cvta_generic_to_shared(sm);

    const int tid  = threadIdx.x;
    const int lane = tid & 31;
    const int wid  = tid >> 5;
    const int Rw   = wid * 16;            // 16 rows per warp, 8 warps = 128 rows

    // ---- zero A1+A2 ----
    for (int i = tid; i < 32768 / 4; i += 256) *(uint32_t*)(sm + A1_OFF + 4 * i) = 0;

    // ---- stage B1/B2a/B2b (hi/lo split + swizzle) ----
    for (int idx = tid; idx < 80 * 64; idx += 256) {
        int n = idx >> 6, k = idx & 63;
        int off = n * 128 + SWZ(n, 2 * k);
        float v; bool lo;
        if (k < 20)      { v = W_hh1[n * HID + k];      lo = false; }
        else if (k < 40) { v = W_hh1[n * HID + k - 20]; lo = false; }
        else if (k < 60) { v = W_hh1[n * HID + k - 40]; lo = true;  }
        else if (k < 62) { v = W_ih1[n];                lo = false; }
        else if (k == 62){ v = W_ih1[n];                lo = true;  }
        else             { v = 0.f;                     lo = false; }
        __nv_bfloat16 vh = __float2bfloat16(v);
        *(__nv_bfloat16*)(sm + B1_OFF + off) =
            lo ? __float2bfloat16(v - __bfloat162float(vh)) : vh;
        float va = (k < 20) ? W_ih2[n * HID + k] : (k < 40) ? W_ih2[n * HID + k - 20]
                 : (k < 60) ? W_ih2[n * HID + k - 40] : 0.f;
        float vb = (k < 20) ? W_hh2[n * HID + k] : (k < 40) ? W_hh2[n * HID + k - 20]
                 : (k < 60) ? W_hh2[n * HID + k - 40] : 0.f;
        bool lo2 = (k >= 40 && k < 60);
        __nv_bfloat16 vah = __float2bfloat16(va), vbh = __float2bfloat16(vb);
        *(__nv_bfloat16*)(sm + B2A_OFF + off) =
            lo2 ? __float2bfloat16(va - __bfloat162float(vah)) : vah;
        *(__nv_bfloat16*)(sm + B2B_OFF + off) =
            lo2 ? __float2bfloat16(vb - __bfloat162float(vbh)) : vbh;
    }
    for (int j = tid; j < HID; j += 256) {
        ((float4*)(sm + BQ1_OFF))[j] = make_float4(
            b_ih1[j] + b_hh1[j], b_ih1[HID + j] + b_hh1[HID + j],
            b_ih1[2*HID + j] + b_hh1[2*HID + j], b_ih1[3*HID + j] + b_hh1[3*HID + j]);
        ((float4*)(sm + BQ2_OFF))[j] = make_float4(
            b_ih2[j] + b_hh2[j], b_ih2[HID + j] + b_hh2[HID + j],
            b_ih2[2*HID + j] + b_hh2[2*HID + j], b_ih2[3*HID + j] + b_hh2[3*HID + j]);
    }
    for (int i = tid; i < FFD * HID; i += 256) ((float*)(sm + W1F_OFF))[i] = W1[i];
    for (int i = tid; i < FFD; i += 256) {
        ((float*)(sm + B1F_OFF))[i] = b1[i];
        ((float*)(sm + W2F_OFF))[i] = W2[i];
    }
    if (tid == 0) *((float*)(sm + B2F_OFF)) = b2[0];
    __syncthreads();

    // epilogue assignment: two threads per row; thread owns 5 gate-quads
    const int rE = Rw + (lane >> 1);            // row this thread post-processes
    const int qs = (lane & 1) * 5;              // quad range start
    const int row_g = blockIdx.x * 128 + rE;    // global row
    const float* __restrict__ xrow = diag + (size_t)min(row_g, rows - 1) * T_LEN;
    char* A1row = sm + A1_OFF + rE * 128;
    char* A2row = sm + A2_OFF + rE * 128;
    const char* zrow = sm + Z_OFF + rE * ZSTRIDE;

    // stage x_0 (one thread per row)
    if (qs == 0) {
        float xv = __ldg(xrow);
        __nv_bfloat16 xh = __float2bfloat16(xv);
        float xhf = __bfloat162float(xh);
        *(uint32_t*)(A1row + SWZ(rE, 120)) = pack2(xv - xhf, xhf);
        *(uint32_t*)(A1row + SWZ(rE, 124)) = (uint32_t)__bfloat16_as_ushort(xh);
    }
    __syncthreads();

    const uint32_t A1w = smb + A1_OFF + Rw * 128;
    const uint32_t A2w = smb + A2_OFF + Rw * 128;
    const float4* bq1 = (const float4*)(sm + BQ1_OFF);
    const float4* bq2 = (const float4*)(sm + BQ2_OFF);

    float c1s[10], c2s[10];
#pragma unroll
    for (int j = 0; j < 10; j++) { c1s[j] = 0.f; c2s[j] = 0.f; }

#pragma unroll 1
    for (int t = 0; t < T_LEN; t++) {
        float cacc[10][4];

        // ---- layer 1: z1 = A1 x B1^T ----
#pragma unroll
        for (int nt = 0; nt < 10; nt++)
#pragma unroll
            for (int e = 0; e < 4; e++) cacc[nt][e] = 0.f;
        gemm_k64(cacc, A1w, smb + B1_OFF, lane);
        store_z(cacc, sm, Rw, lane);
        __syncwarp();
        epilogue(zrow, bq1, c1s, A1row, rE, qs);   // h1(t) -> A1
        __syncwarp();

        // ---- layer 2: z2 = A1 x B2a^T + A2 x B2b^T ----
#pragma unroll
        for (int nt = 0; nt < 10; nt++)
#pragma unroll
            for (int e = 0; e < 4; e++) cacc[nt][e] = 0.f;
        gemm_k64(cacc, A1w, smb + B2A_OFF, lane);
        gemm_k64(cacc, A2w, smb + B2B_OFF, lane);
        store_z(cacc, sm, Rw, lane);
        __syncwarp();
        epilogue(zrow, bq2, c2s, A2row, rE, qs);   // h2(t) -> A2
        if (t + 1 < T_LEN && qs == 0) {            // stage x_{t+1}
            float xv = __ldg(xrow + t + 1);
            __nv_bfloat16 xh = __float2bfloat16(xv);
            float xhf = __bfloat162float(xh);
            *(uint32_t*)(A1row + SWZ(rE, 120)) = pack2(xv - xhf, xhf);
            *(uint32_t*)(A1row + SWZ(rE, 124)) = (uint32_t)__bfloat16_as_ushort(xh);
        }
        __syncwarp();
    }

    // ---- head: h2 = hi + lo from A2; each thread does 32 of 64 FF units, pair-combine ----
    float h2f[HID];
#pragma unroll
    for (int q = 0; q < 10; q++) {
        uint32_t hi = *(uint32_t*)(A2row + SWZ(rE, 4 * q));
        uint32_t lo = *(uint32_t*)(A2row + SWZ(rE, 40 + 4 * q));
        h2f[2*q]     = __uint_as_float(hi << 16) + __uint_as_float(lo << 16);
        h2f[2*q + 1] = __uint_as_float(hi & 0xFFFF0000u) + __uint_as_float(lo & 0xFFFF0000u);
    }
    const float* W1f = (const float*)(sm + W1F_OFF);
    const float* b1f = (const float*)(sm + B1F_OFF);
    const float* W2f = (const float*)(sm + W2F_OFF);
    float acc2 = (qs == 0) ? *((const float*)(sm + B2F_OFF)) : 0.0f;
    const int n0 = (qs == 0) ? 0 : 32;
#pragma unroll 1
    for (int n = n0; n < n0 + 32; n++) {
        float a = b1f[n];
#pragma unroll
        for (int k = 0; k < HID; k++) a = fmaf(W1f[n * HID + k], h2f[k], a);
        acc2 = fmaf(W2f[n], fmaxf(a, 0.0f), acc2);
    }
    acc2 += __shfl_xor_sync(0xFFFFFFFFu, acc2, 1);
    if (qs == 0 && row_g < rows) out[row_g] = fmaxf(acc2, 0.0f);
}

extern "C" void kernel_launch(void* const* d_in, const int* in_sizes, int n_in,
                              void* d_out, int out_size) {
    const float* diag  = (const float*)d_in[0];
    const float* W_ih1 = (const float*)d_in[1];
    const float* W_hh1 = (const float*)d_in[2];
    const float* b_ih1 = (const float*)d_in[3];
    const float* b_hh1 = (const float*)d_in[4];
    const float* W_ih2 = (const float*)d_in[5];
    const float* W_hh2 = (const float*)d_in[6];
    const float* b_ih2 = (const float*)d_in[7];
    const float* b_hh2 = (const float*)d_in[8];
    const float* W1    = (const float*)d_in[9];
    const float* b1    = (const float*)d_in[10];
    const float* W2    = (const float*)d_in[11];
    const float* b2    = (const float*)d_in[12];

    int rows = out_size;   // 131072
    int blocks = (rows + 127) / 128;   // 128 rows per CTA

    cudaFuncSetAttribute(lstm2_mma_kernel,
                         cudaFuncAttributeMaxDynamicSharedMemorySize, DYN_BYTES);

    lstm2_mma_kernel<<<blocks, 256, DYN_BYTES>>>(
        diag, W_ih1, W_hh1, b_ih1, b_hh1,
        W_ih2, W_hh2, b_ih2, b_hh2,
        W1, b1, W2, b2, (float*)d_out, rows);
}

// round 9
// speedup vs baseline: 2.7656x; 1.3043x over previous
#include <cuda_runtime.h>
#include <cuda_bf16.h>
#include <cstdint>

#define T_LEN 256
#define HID   20
#define FFD   64

// dynamic smem offsets (from 128-aligned base)
#define A1_OFF   0        // [128][64 bf16] rows=batch: [h1_hi(20)|h1_lo(20)|h1_hi(20)|xh,xl,xh,pad]
#define A2_OFF   16384    // [128][64 bf16] [h2_hi|h2_lo|h2_hi|pad4]
#define B1_OFF   32768    // [80][64 bf16]  gate-interleaved rows (see staging)
#define B2A_OFF  43008    // [80][64]
#define B2B_OFF  53248    // [80][64]
#define BQ1_OFF  63488    // 20 x float4 gate-quad biases (per unit)
#define BQ2_OFF  63808
#define W1F_OFF  64128    // head W1 [64][20] f32
#define B1F_OFF  69248
#define W2F_OFF  69504
#define B2F_OFF  69760
#define DYN_BYTES 70144

#define SWZ(row, b) ((b) ^ (((row) & 7) << 4))

__device__ __forceinline__ float tanhap(float x) {
    float r; asm("tanh.approx.f32 %0, %1;" : "=f"(r) : "f"(x)); return r;
}
__device__ __forceinline__ float sigm(float x) {
    return fmaf(0.5f, tanhap(0.5f * x), 0.5f);
}
__device__ __forceinline__ uint32_t pack2(float hi_val, float lo_val) {
    uint32_t r;
    asm("cvt.rn.bf16x2.f32 %0, %1, %2;" : "=r"(r) : "f"(hi_val), "f"(lo_val));
    return r;
}
__device__ __forceinline__ void ldsm4(uint32_t* r, uint32_t a) {
    asm volatile("ldmatrix.sync.aligned.m8n8.x4.shared.b16 {%0,%1,%2,%3}, [%4];"
                 : "=r"(r[0]), "=r"(r[1]), "=r"(r[2]), "=r"(r[3]) : "r"(a));
}
__device__ __forceinline__ void mma16816(float* c, const uint32_t* a, const uint32_t* b) {
    asm volatile(
        "mma.sync.aligned.m16n8k16.row.col.f32.bf16.bf16.f32 "
        "{%0,%1,%2,%3}, {%4,%5,%6,%7}, {%8,%9}, {%0,%1,%2,%3};"
        : "+f"(c[0]), "+f"(c[1]), "+f"(c[2]), "+f"(c[3])
        : "r"(a[0]), "r"(a[1]), "r"(a[2]), "r"(a[3]), "r"(b[0]), "r"(b[1]));
}

// A fragment address for a 16-row tile at 'base' (row-major 128B rows, SW128)
__device__ __forceinline__ uint32_t a_addr(uint32_t base, int ks, int lane) {
    int sub = lane >> 3, lr = lane & 7;
    int row = ((sub & 1) << 3) + lr;
    int cb  = ks * 32 + ((sub >> 1) << 4);
    return base + row * 128 + SWZ(row, cb);
}
// B fragment address: regs {0,1}=n-tile 2np, {2,3}=2np+1
__device__ __forceinline__ uint32_t b_addr(uint32_t base, int np, int ks, int lane) {
    int sub = lane >> 3, lr = lane & 7;
    int row = np * 16 + ((sub >> 1) << 3) + lr;
    int cb  = ks * 32 + ((sub & 1) << 4);
    return base + row * 128 + SWZ(row, cb);
}

// one K=64 pass for M=16: accumulate into cacc[10][4]
__device__ __forceinline__ void gemm_k64(float cacc[10][4], uint32_t aB, uint32_t bB, int lane) {
#pragma unroll
    for (int ks = 0; ks < 4; ks++) {
        uint32_t a0[4];
        ldsm4(a0, a_addr(aB, ks, lane));
#pragma unroll
        for (int np = 0; np < 5; np++) {
            uint32_t b[4];
            ldsm4(b, b_addr(bB, np, ks, lane));
            mma16816(cacc[2*np],     a0, b);
            mma16816(cacc[2*np + 1], a0, b + 2);
        }
    }
}

// Register epilogue. Thread (m=lane&3): s = m>>1, odd = m&1.
// Owns gate-pair ((i,f) if even m else (g,o)) of unit u = nt + 10*s,
// rows r0 (regs c0,c1) and r0+8 (c2,c3). Partner lane^1 holds the other pair.
// After shfl: even-m handles row r0, odd-m handles row r0+8, full quad each.
__device__ __forceinline__ void epilogue_reg(float cacc[10][4], const float4* bq, float* cs,
                                             char* arow, int rEp, int odd, int s) {
#pragma unroll
    for (int a = 0; a < 5; a++) {
        float h01[2];
#pragma unroll
        for (int e = 0; e < 2; e++) {
            int nt = 2 * a + e;
            float s0 = odd ? cacc[nt][0] : cacc[nt][2];
            float s1 = odd ? cacc[nt][1] : cacc[nt][3];
            float p0 = __shfl_xor_sync(0xFFFFFFFFu, s0, 1);
            float p1 = __shfl_xor_sync(0xFFFFFFFFu, s1, 1);
            float zi = odd ? p0 : cacc[nt][0];
            float zf = odd ? p1 : cacc[nt][1];
            float zg = odd ? cacc[nt][2] : p0;
            float zo = odd ? cacc[nt][3] : p1;
            float4 b4 = bq[nt + 10 * s];
            float ii = sigm(zi + b4.x);
            float ff = sigm(zf + b4.y);
            float gg = tanhap(zg + b4.z);
            float oo = sigm(zo + b4.w);
            float cc = fmaf(ff, cs[nt], ii * gg); cs[nt] = cc;
            h01[e] = oo * tanhap(cc);
        }
        uint32_t hi = pack2(h01[1], h01[0]);
        float r0f = __uint_as_float(hi << 16);
        float r1f = __uint_as_float(hi & 0xFFFF0000u);
        uint32_t lo = pack2(h01[1] - r1f, h01[0] - r0f);
        int ub = 2 * (2 * a + 10 * s);   // byte offset of this unit pair
        *(uint32_t*)(arow + SWZ(rEp, ub))      = hi;   // hi   (cols 0-19)
        *(uint32_t*)(arow + SWZ(rEp, 40 + ub)) = lo;   // lo   (cols 20-39)
        *(uint32_t*)(arow + SWZ(rEp, 80 + ub)) = hi;   // hi dup (cols 40-59)
    }
}

__global__ void __launch_bounds__(256, 2) lstm2_mma_kernel(
    const float* __restrict__ diag,
    const float* __restrict__ W_ih1, const float* __restrict__ W_hh1,
    const float* __restrict__ b_ih1, const float* __restrict__ b_hh1,
    const float* __restrict__ W_ih2, const float* __restrict__ W_hh2,
    const float* __restrict__ b_ih2, const float* __restrict__ b_hh2,
    const float* __restrict__ W1,   const float* __restrict__ b1,
    const float* __restrict__ W2,   const float* __restrict__ b2,
    float* __restrict__ out, int rows)
{
    extern __shared__ char rawsm[];
    char* sm = (char*)(((uintptr_t)rawsm + 127) & ~(uintptr_t)127);
    const uint32_t smb = (uint32_t)__cvta_generic_to_shared(sm);

    const int tid  = threadIdx.x;
    const int lane = tid & 31;
    const int wid  = tid >> 5;
    const int Rw   = wid * 16;            // 16 rows per warp, 8 warps = 128 rows

    // ---- zero A1+A2 ----
    for (int i = tid; i < 32768 / 4; i += 256) *(uint32_t*)(sm + A1_OFF + 4 * i) = 0;

    // ---- stage B tiles: row n <-> (gate = n&3, unit = (n>>3) + 10*((n>>2)&1)) ----
    for (int idx = tid; idx < 80 * 64; idx += 256) {
        int n = idx >> 6, k = idx & 63;
        int off = n * 128 + SWZ(n, 2 * k);
        int wr = (n & 3) * HID + ((n >> 3) + 10 * ((n >> 2) & 1));  // row in original [80]
        // layer 1: [Whh_hi(20) | Whh_hi(20) | Whh_lo(20) | Wx_hi, Wx_hi, Wx_lo, 0]
        float v; bool lo;
        if (k < 20)      { v = W_hh1[wr * HID + k];      lo = false; }
        else if (k < 40) { v = W_hh1[wr * HID + k - 20]; lo = false; }
        else if (k < 60) { v = W_hh1[wr * HID + k - 40]; lo = true;  }
        else if (k < 62) { v = W_ih1[wr];                lo = false; }
        else if (k == 62){ v = W_ih1[wr];                lo = true;  }
        else             { v = 0.f;                      lo = false; }
        __nv_bfloat16 vh = __float2bfloat16(v);
        *(__nv_bfloat16*)(sm + B1_OFF + off) =
            lo ? __float2bfloat16(v - __bfloat162float(vh)) : vh;
        float va = (k < 20) ? W_ih2[wr * HID + k] : (k < 40) ? W_ih2[wr * HID + k - 20]
                 : (k < 60) ? W_ih2[wr * HID + k - 40] : 0.f;
        float vb = (k < 20) ? W_hh2[wr * HID + k] : (k < 40) ? W_hh2[wr * HID + k - 20]
                 : (k < 60) ? W_hh2[wr * HID + k - 40] : 0.f;
        bool lo2 = (k >= 40 && k < 60);
        __nv_bfloat16 vah = __float2bfloat16(va), vbh = __float2bfloat16(vb);
        *(__nv_bfloat16*)(sm + B2A_OFF + off) =
            lo2 ? __float2bfloat16(va - __bfloat162float(vah)) : vah;
        *(__nv_bfloat16*)(sm + B2B_OFF + off) =
            lo2 ? __float2bfloat16(vb - __bfloat162float(vbh)) : vbh;
    }
    for (int j = tid; j < HID; j += 256) {
        ((float4*)(sm + BQ1_OFF))[j] = make_float4(
            b_ih1[j] + b_hh1[j], b_ih1[HID + j] + b_hh1[HID + j],
            b_ih1[2*HID + j] + b_hh1[2*HID + j], b_ih1[3*HID + j] + b_hh1[3*HID + j]);
        ((float4*)(sm + BQ2_OFF))[j] = make_float4(
            b_ih2[j] + b_hh2[j], b_ih2[HID + j] + b_hh2[HID + j],
            b_ih2[2*HID + j] + b_hh2[2*HID + j], b_ih2[3*HID + j] + b_hh2[3*HID + j]);
    }
    for (int i = tid; i < FFD * HID; i += 256) ((float*)(sm + W1F_OFF))[i] = W1[i];
    for (int i = tid; i < FFD; i += 256) {
        ((float*)(sm + B1F_OFF))[i] = b1[i];
        ((float*)(sm + W2F_OFF))[i] = W2[i];
    }
    if (tid == 0) *((float*)(sm + B2F_OFF)) = b2[0];
    __syncthreads();

    const int m    = lane & 3;
    const int odd  = m & 1;
    const int s    = m >> 1;
    const int rEp  = Rw + (lane >> 2) + (odd ? 8 : 0);   // row this thread post-processes
    const int row_g = blockIdx.x * 128 + rEp;
    const float* __restrict__ xrow = diag + (size_t)min(row_g, rows - 1) * T_LEN;
    char* A1row = sm + A1_OFF + rEp * 128;
    char* A2row = sm + A2_OFF + rEp * 128;

    // stage x_0 (one thread per row: m < 2 covers rows r0 (m=0) and r0+8 (m=1))
    if (m < 2) {
        float xv = __ldg(xrow);
        __nv_bfloat16 xh = __float2bfloat16(xv);
        float xhf = __bfloat162float(xh);
        *(uint32_t*)(A1row + SWZ(rEp, 120)) = pack2(xv - xhf, xhf);
        *(uint32_t*)(A1row + SWZ(rEp, 124)) = (uint32_t)__bfloat16_as_ushort(xh);
    }
    __syncthreads();

    const uint32_t A1w = smb + A1_OFF + Rw * 128;
    const uint32_t A2w = smb + A2_OFF + Rw * 128;
    const float4* bq1 = (const float4*)(sm + BQ1_OFF);
    const float4* bq2 = (const float4*)(sm + BQ2_OFF);

    float c1s[10], c2s[10];
#pragma unroll
    for (int j = 0; j < 10; j++) { c1s[j] = 0.f; c2s[j] = 0.f; }

#pragma unroll 1
    for (int t = 0; t < T_LEN; t++) {
        float cacc[10][4];

        // ---- layer 1: z1 = A1 x B1^T ----
#pragma unroll
        for (int nt = 0; nt < 10; nt++)
#pragma unroll
            for (int e = 0; e < 4; e++) cacc[nt][e] = 0.f;
        gemm_k64(cacc, A1w, smb + B1_OFF, lane);
        epilogue_reg(cacc, bq1, c1s, A1row, rEp, odd, s);   // h1(t) -> A1
        __syncwarp();

        // ---- layer 2: z2 = A1 x B2a^T + A2 x B2b^T ----
#pragma unroll
        for (int nt = 0; nt < 10; nt++)
#pragma unroll
            for (int e = 0; e < 4; e++) cacc[nt][e] = 0.f;
        gemm_k64(cacc, A1w, smb + B2A_OFF, lane);
        gemm_k64(cacc, A2w, smb + B2B_OFF, lane);
        epilogue_reg(cacc, bq2, c2s, A2row, rEp, odd, s);   // h2(t) -> A2
        if (t + 1 < T_LEN && m < 2) {                        // stage x_{t+1}
            float xv = __ldg(xrow + t + 1);
            __nv_bfloat16 xh = __float2bfloat16(xv);
            float xhf = __bfloat162float(xh);
            *(uint32_t*)(A1row + SWZ(rEp, 120)) = pack2(xv - xhf, xhf);
            *(uint32_t*)(A1row + SWZ(rEp, 124)) = (uint32_t)__bfloat16_as_ushort(xh);
        }
        __syncwarp();
    }

    // ---- head: h2 = hi + lo from A2; FF split by s, combine over lane^2 ----
    float h2f[HID];
#pragma unroll
    for (int q = 0; q < 10; q++) {
        uint32_t hi = *(uint32_t*)(A2row + SWZ(rEp, 4 * q));
        uint32_t lo = *(uint32_t*)(A2row + SWZ(rEp, 40 + 4 * q));
        h2f[2*q]     = __uint_as_float(hi << 16) + __uint_as_float(lo << 16);
        h2f[2*q + 1] = __uint_as_float(hi & 0xFFFF0000u) + __uint_as_float(lo & 0xFFFF0000u);
    }
    const float* W1f = (const float*)(sm + W1F_OFF);
    const float* b1f = (const float*)(sm + B1F_OFF);
    const float* W2f = (const float*)(sm + W2F_OFF);
    float acc2 = (s == 0) ? *((const float*)(sm + B2F_OFF)) : 0.0f;
    const int n0 = s * 32;
#pragma unroll 1
    for (int n = n0; n < n0 + 32; n++) {
        float a = b1f[n];
#pragma unroll
        for (int k = 0; k < HID; k++) a = fmaf(W1f[n * HID + k], h2f[k], a);
        acc2 = fmaf(W2f[n], fmaxf(a, 0.0f), acc2);
    }
    acc2 += __shfl_xor_sync(0xFFFFFFFFu, acc2, 2);   // combine the two s halves (same row)
    if (s == 0 && row_g < rows) out[row_g] = fmaxf(acc2, 0.0f);
}

extern "C" void kernel_launch(void* const* d_in, const int* in_sizes, int n_in,
                              void* d_out, int out_size) {
    const float* diag  = (const float*)d_in[0];
    const float* W_ih1 = (const float*)d_in[1];
    const float* W_hh1 = (const float*)d_in[2];
    const float* b_ih1 = (const float*)d_in[3];
    const float* b_hh1 = (const float*)d_in[4];
    const float* W_ih2 = (const float*)d_in[5];
    const float* W_hh2 = (const float*)d_in[6];
    const float* b_ih2 = (const float*)d_in[7];
    const float* b_hh2 = (const float*)d_in[8];
    const float* W1    = (const float*)d_in[9];
    const float* b1    = (const float*)d_in[10];
    const float* W2    = (const float*)d_in[11];
    const float* b2    = (const float*)d_in[12];

    int rows = out_size;   // 131072
    int blocks = (rows + 127) / 128;   // 128 rows per CTA

    cudaFuncSetAttribute(lstm2_mma_kernel,
                         cudaFuncAttributeMaxDynamicSharedMemorySize, DYN_BYTES);

    lstm2_mma_kernel<<<blocks, 256, DYN_BYTES>>>(
        diag, W_ih1, W_hh1, b_ih1, b_hh1,
        W_ih2, W_hh2, b_ih2, b_hh2,
        W1, b1, W2, b2, (float*)d_out, rows);
}